// round 15
// baseline (speedup 1.0000x reference)
#include <cuda_runtime.h>
#include <cstdint>
#include <math.h>

#define BB 2
#define SS 2048
#define DD 1024
#define HH 16
#define HDD 64
#define MTOT (BB * SS)      // 4096
#define NQKV (3 * DD)       // 3072

// ---------------- device scratch (no allocation allowed) -------------------
__device__ float g_q[BB * HH * SS * HDD];   // tf32-rounded, scaled by 0.125*log2(e)
__device__ float g_k[BB * HH * SS * HDD];   // tf32-rounded
__device__ float g_v[BB * HH * SS * HDD];   // tf32-rounded
__device__ float g_attn[MTOT * DD];         // flash out, tf32-rounded
__device__ float g_xr[MTOT * DD];           // tf32-rounded x
__device__ float g_wqkvr[NQKV * DD];        // tf32-rounded w_qkv
__device__ float g_wprojr[DD * DD];         // tf32-rounded w_proj
__device__ float2 g_cs[SS * (HDD / 2)];     // cos/sin table

// ---------------- helpers ---------------------------------------------------
__device__ __forceinline__ uint32_t smem_u32(const void* p) {
    uint32_t a;
    asm("{ .reg .u64 t; cvta.to.shared.u64 t, %1; cvt.u32.u64 %0, t; }"
        : "=r"(a) : "l"(p));
    return a;
}
__device__ __forceinline__ float tf32r(float x) {
    float y;
    asm("cvt.rna.tf32.f32 %0, %1;" : "=f"(y) : "f"(x));
    return y;
}
__device__ __forceinline__ float ex2(float x) {
    float y;
    asm("ex2.approx.f32 %0, %1;" : "=f"(y) : "f"(x));
    return y;
}
__device__ __forceinline__ void mma_tf32(
    float& c0, float& c1, float& c2, float& c3,
    uint32_t a0, uint32_t a1, uint32_t a2, uint32_t a3,
    uint32_t b0, uint32_t b1)
{
    asm volatile(
        "mma.sync.aligned.m16n8k8.row.col.f32.tf32.tf32.f32 "
        "{%0,%1,%2,%3}, {%4,%5,%6,%7}, {%8,%9}, {%0,%1,%2,%3};"
        : "+f"(c0), "+f"(c1), "+f"(c2), "+f"(c3)
        : "r"(a0), "r"(a1), "r"(a2), "r"(a3), "r"(b0), "r"(b1));
}
// ldmatrix x4: four 8x16B matrices; thread t gets word (t&3) of row (t>>2)
// of matrix j in reg j. Lanes 0-7 address matrix0 rows, 8-15 matrix1, etc.
__device__ __forceinline__ void ldsm_x4(
    uint32_t& r0, uint32_t& r1, uint32_t& r2, uint32_t& r3, uint32_t addr)
{
    asm volatile(
        "ldmatrix.sync.aligned.m8n8.x4.shared.b16 {%0,%1,%2,%3}, [%4];"
        : "=r"(r0), "=r"(r1), "=r"(r2), "=r"(r3) : "r"(addr));
}
#define CPASYNC16(dst, src) \
    asm volatile("cp.async.cg.shared.global [%0], [%1], 16;" :: "r"(dst), "l"(src))
#define CPCOMMIT() asm volatile("cp.async.commit_group;")

// ---------------------------------------------------------------------------
// tf32 mma.sync GEMM mainloop — R11 pipeline (3-stage, 2 barriers, frozen),
// fragment loads via ldmatrix.x4: 6 LDSM per ks-step instead of 24 LDS.
// Smem layout: float (r,c) at r*32 + (((c>>2)^(r&7))<<2) + (c&3).
// ---------------------------------------------------------------------------
#define GSTAGES 3
#define GTILE_B 16384                        // 128*32*4
#define GSTAGE_B (2 * GTILE_B)               // 32768
#define GEMM_SMEM (GSTAGES * GSTAGE_B)       // 98304

__device__ __forceinline__ void g_load_stage(
    uint32_t sbase, const float* A, const float* W, int K,
    int bm, int bn, int buf, int it, int tid)
{
    uint32_t sa = sbase + buf * GSTAGE_B;
    uint32_t sw = sa + GTILE_B;
    const float* Ag = A + (size_t)bm * K + it * 32;
    const float* Wg = W + (size_t)bn * K + it * 32;
    #pragma unroll
    for (int i = 0; i < 4; i++) {
        int idx = tid + (i << 8);            // 0..1023
        int row = idx >> 3, cc = idx & 7;
        uint32_t off = (row * 32 + ((cc ^ (row & 7)) << 2)) * 4;
        CPASYNC16(sa + off, Ag + (size_t)row * K + (cc << 2));
        CPASYNC16(sw + off, Wg + (size_t)row * K + (cc << 2));
    }
    CPCOMMIT();
}

// e = lane&7; a_rb/b_rb are per-thread ldmatrix row-base byte offsets.
#define GEMM_MAINLOOP(A_, W_, K_)                                              \
    float acc[4][4][4];                                                        \
    _Pragma("unroll") for (int mi = 0; mi < 4; mi++)                           \
        _Pragma("unroll") for (int ni = 0; ni < 4; ni++)                       \
            _Pragma("unroll") for (int e2 = 0; e2 < 4; e2++) acc[mi][ni][e2] = 0.f;\
    const uint32_t a_rb = ((wm << 6) + ((lane >> 3) << 4) + e) * 128;          \
    const uint32_t b_rb = ((wn << 5) + lane) * 128;                            \
    const int niter = (K_) >> 5;                                               \
    for (int s = 0; s < GSTAGES; s++)                                          \
        g_load_stage(sb, A_, W_, K_, bm, bn, s, s, tid);                       \
    for (int i = 0; i < niter; i++) {                                          \
        const int buf = i % GSTAGES;                                           \
        asm volatile("cp.async.wait_group 2;" ::: "memory");                   \
        __syncthreads();                                                       \
        const uint32_t As_a = sb + buf * GSTAGE_B;                             \
        const uint32_t Ws_a = As_a + GTILE_B;                                  \
        _Pragma("unroll")                                                      \
        for (int ks = 0; ks < 4; ks++) {                                       \
            const uint32_t off0 = (((ks << 1) ^ e) << 4);                      \
            const uint32_t off1 = ((((ks << 1) | 1) ^ e) << 4);                \
            uint32_t a0[4], a1v[4], a2v[4], a3v[4], bf0[4], bf1[4];            \
            ldsm_x4(a0[0],  a0[1],  a0[2],  a0[3],  As_a + a_rb + off0);       \
            ldsm_x4(a1v[0], a1v[1], a1v[2], a1v[3], As_a + a_rb + 1024 + off0);\
            ldsm_x4(a2v[0], a2v[1], a2v[2], a2v[3], As_a + a_rb + off1);       \
            ldsm_x4(a3v[0], a3v[1], a3v[2], a3v[3], As_a + a_rb + 1024 + off1);\
            ldsm_x4(bf0[0], bf0[1], bf0[2], bf0[3], Ws_a + b_rb + off0);       \
            ldsm_x4(bf1[0], bf1[1], bf1[2], bf1[3], Ws_a + b_rb + off1);       \
            _Pragma("unroll") for (int mi = 0; mi < 4; mi++)                   \
                _Pragma("unroll") for (int ni = 0; ni < 4; ni++)               \
                    mma_tf32(acc[mi][ni][0], acc[mi][ni][1],                   \
                             acc[mi][ni][2], acc[mi][ni][3],                   \
                             a0[mi], a1v[mi], a2v[mi], a3v[mi],                \
                             bf0[ni], bf1[ni]);                                \
        }                                                                      \
        __syncthreads();                                                       \
        if (i + GSTAGES < niter)                                               \
            g_load_stage(sb, A_, W_, K_, bm, bn, buf, i + GSTAGES, tid);       \
        else                                                                   \
            CPCOMMIT();                                                        \
    }

// ---------------------------------------------------------------------------
// Generic GEMM (proj): C = A @ W^T + bias
// ---------------------------------------------------------------------------
__global__ void __launch_bounds__(256, 2) gemm_mma_tf32(
    const float* __restrict__ A, const float* __restrict__ W,
    const float* __restrict__ bias, float* __restrict__ C,
    int M, int N, int K)
{
    extern __shared__ char smem[];
    uint32_t sb = smem_u32(smem);
    const int tid  = threadIdx.x;
    const int lane = tid & 31;
    const int wid  = tid >> 5;
    const int wm   = wid >> 2, wn = wid & 3;
    const int bm = blockIdx.y << 7, bn = blockIdx.x << 7;
    const int lr = lane >> 2, lq = lane & 3;
    const int e  = lane & 7;

    GEMM_MAINLOOP(A, W, K)

    #pragma unroll
    for (int mi = 0; mi < 4; mi++) {
        const int row = bm + (wm << 6) + (mi << 4) + lr;
        #pragma unroll
        for (int ni = 0; ni < 4; ni++) {
            const int col = bn + (wn << 5) + (ni << 3) + (lq << 1);
            const float b0 = bias[col], b1 = bias[col + 1];
            *(float2*)&C[(size_t)row * N + col] =
                make_float2(acc[mi][ni][0] + b0, acc[mi][ni][1] + b1);
            *(float2*)&C[(size_t)(row + 8) * N + col] =
                make_float2(acc[mi][ni][2] + b0, acc[mi][ni][3] + b1);
        }
    }
}

// ---------------------------------------------------------------------------
// QKV GEMM with fused RoPE epilogue -> q (rot, *0.125*log2e), k (rot), v,
// all tf32-rounded, [B,H,S,HD] layout.
// ---------------------------------------------------------------------------
#define QSCALE (0.125f * 1.4426950408889634f)

__global__ void __launch_bounds__(256, 2) gemm_qkv_rope(
    const float* __restrict__ A, const float* __restrict__ W,
    const float* __restrict__ bias, const float2* __restrict__ cs,
    float* __restrict__ qo, float* __restrict__ ko, float* __restrict__ vo,
    int K)
{
    extern __shared__ char smem[];
    uint32_t sb = smem_u32(smem);
    const int tid  = threadIdx.x;
    const int lane = tid & 31;
    const int wid  = tid >> 5;
    const int wm   = wid >> 2, wn = wid & 3;
    const int bm = blockIdx.y << 7, bn = blockIdx.x << 7;
    const int lr = lane >> 2, lq = lane & 3;
    const int e  = lane & 7;

    GEMM_MAINLOOP(A, W, K)

    const int sec = bn >> 10;   // 0=q, 1=k, 2=v (uniform per CTA)
    #pragma unroll
    for (int mi = 0; mi < 4; mi++) {
        #pragma unroll
        for (int ni = 0; ni < 4; ni++) {
            const int col = bn + (wn << 5) + (ni << 3) + (lq << 1);
            const int h   = (col >> 6) & 15;
            const int d2  = (col & 63) >> 1;
            const float b0 = bias[col], b1 = bias[col + 1];
            #pragma unroll
            for (int hf = 0; hf < 2; hf++) {
                const int row = bm + (wm << 6) + (mi << 4) + lr + (hf << 3);
                const int b = row >> 11, s = row & 2047;
                const float v0 = acc[mi][ni][2 * hf]     + b0;
                const float v1 = acc[mi][ni][2 * hf + 1] + b1;
                const size_t o =
                    ((size_t)((b * HH + h) * SS + s)) * HDD + (d2 << 1);
                if (sec == 2) {
                    *(float2*)&vo[o] = make_float2(tf32r(v0), tf32r(v1));
                } else {
                    const float2 t = cs[s * 32 + d2];
                    float r0 = v0 * t.x - v1 * t.y;
                    float r1 = v0 * t.y + v1 * t.x;
                    if (sec == 0) {
                        *(float2*)&qo[o] = make_float2(tf32r(r0 * QSCALE),
                                                       tf32r(r1 * QSCALE));
                    } else {
                        *(float2*)&ko[o] = make_float2(tf32r(r0), tf32r(r1));
                    }
                }
            }
        }
    }
}

// ---------------------------------------------------------------------------
// Fused prep: tf32-round x / w_qkv / w_proj + build cos/sin table. 1 launch.
// ---------------------------------------------------------------------------
#define NX4 (MTOT * DD / 4)                  // 1048576
#define NW4 (NQKV * DD / 4)                  // 786432
#define NP4 (DD * DD / 4)                    // 262144
#define NPREP (NX4 + NW4 + NP4)              // 2097152

__global__ void prep_kernel(
    const float4* __restrict__ x,  const float4* __restrict__ wq,
    const float4* __restrict__ wp, const float* __restrict__ freqs,
    float4* __restrict__ xr, float4* __restrict__ wqr,
    float4* __restrict__ wpr, float2* __restrict__ cs)
{
    const int i = blockIdx.x * blockDim.x + threadIdx.x;
    if (i < NPREP) {
        const float4* src;
        float4* dst;
        int j;
        if (i < NX4)            { src = x;  dst = xr;  j = i; }
        else if (i < NX4 + NW4) { src = wq; dst = wqr; j = i - NX4; }
        else                    { src = wp; dst = wpr; j = i - NX4 - NW4; }
        float4 v = src[j];
        v.x = tf32r(v.x); v.y = tf32r(v.y); v.z = tf32r(v.z); v.w = tf32r(v.w);
        dst[j] = v;
    }
    if (i < SS * 32) {
        float f = freqs[i];
        cs[i] = make_float2(cosf(f), sinf(f));
    }
}

// ---------------------------------------------------------------------------
// Flash attention — R14 winner, FROZEN.
// Static exp2 softmax (ex2.approx), raw-fp32 P (HW tf32 truncation),
// deferred lrow reduction, BQ=BK=64, 128 thr, cp.async double-buffered K/V,
// heavy-tiles-first. smem 106496 B, 2 CTAs/SM.
// ---------------------------------------------------------------------------
#define QS_STR 68
#define VS_STR 72
#define FA_QS 0
#define FA_PS (64 * QS_STR)
#define FA_K0 (2 * 64 * QS_STR)            // + buf*64*QS_STR
#define FA_V0 (4 * 64 * QS_STR)            // + buf*64*VS_STR
#define FA_SMEM ((4 * 64 * QS_STR + 2 * 64 * VS_STR) * 4)   // 106496 bytes

__device__ __forceinline__ void fa_load_kv(
    uint32_t sbq, const float* Kb, const float* Vb, int k0, int buf, int tid)
{
    uint32_t ks = sbq + (FA_K0 + buf * 64 * QS_STR) * 4;
    uint32_t vs = sbq + (FA_V0 + buf * 64 * VS_STR) * 4;
    #pragma unroll
    for (int i = 0; i < 8; i++) {
        int idx = tid + (i << 7);          // 0..1023
        int r = idx >> 4, c4 = (idx & 15) << 2;
        CPASYNC16(ks + (r * QS_STR + c4) * 4, Kb + (size_t)(k0 + r) * HDD + c4);
        CPASYNC16(vs + (r * VS_STR + c4) * 4, Vb + (size_t)(k0 + r) * HDD + c4);
    }
    CPCOMMIT();
}

__global__ void __launch_bounds__(128) flash_mma_kernel(
    const float* __restrict__ Q, const float* __restrict__ K,
    const float* __restrict__ V, float* __restrict__ O)
{
    extern __shared__ float sm[];
    uint32_t sbq = smem_u32(sm);
    float* Qs = sm + FA_QS;
    float* Ps = sm + FA_PS;
    const uint32_t* Qu = (const uint32_t*)Qs;
    const uint32_t* Pu = (const uint32_t*)Ps;

    const int tid  = threadIdx.x;
    const int lane = tid & 31;
    const int wid  = tid >> 5;
    const int lr   = lane >> 2, lq = lane & 3;
    const int wm   = wid << 4;
    const int qt   = gridDim.x - 1 - blockIdx.x;   // heavy tiles first
    const int q0   = qt << 6;
    const int bh   = blockIdx.y;

    const float* Qb = Q + ((size_t)bh * SS + q0) * HDD;
    const float* Kb = K + (size_t)bh * SS * HDD;
    const float* Vb = V + (size_t)bh * SS * HDD;

    const int ntiles = qt + 1;
    fa_load_kv(sbq, Kb, Vb, 0, 0, tid);

    // Q tile (already rounded+scaled by 0.125*log2e)
    #pragma unroll
    for (int i = 0; i < 8; i++) {
        int idx = tid + (i << 7);
        int r = idx >> 4, c4 = (idx & 15) << 2;
        float4 t = *(const float4*)(Qb + r * HDD + c4);
        *(float4*)&Qs[r * QS_STR + c4] = t;
    }

    float lrow[2], oacc[8][4];
    lrow[0] = lrow[1] = 0.f;          // per-thread partial; warp-reduced once
    #pragma unroll
    for (int j = 0; j < 8; j++)
        #pragma unroll
        for (int e = 0; e < 4; e++) oacc[j][e] = 0.f;

    for (int t = 0; t < ntiles; t++) {
        if (t + 1 < ntiles) {
            fa_load_kv(sbq, Kb, Vb, (t + 1) << 6, (t + 1) & 1, tid);
            asm volatile("cp.async.wait_group 1;" ::: "memory");
        } else {
            asm volatile("cp.async.wait_group 0;" ::: "memory");
        }
        __syncthreads();

        const uint32_t* Ku = (const uint32_t*)(sm + FA_K0 + (t & 1) * 64 * QS_STR);
        const uint32_t* Vu = (const uint32_t*)(sm + FA_V0 + (t & 1) * 64 * VS_STR);

        // S' = Q K^T  (log2-domain scores; warp: m16 x n64, k64)
        float sc[8][4];
        #pragma unroll
        for (int j = 0; j < 8; j++)
            #pragma unroll
            for (int e = 0; e < 4; e++) sc[j][e] = 0.f;
        #pragma unroll
        for (int ks = 0; ks < 8; ks++) {
            const int kc = (ks << 3) + lq;
            const int ar = wm + lr;
            uint32_t a0 = Qu[ar * QS_STR + kc];
            uint32_t a1 = Qu[(ar + 8) * QS_STR + kc];
            uint32_t a2 = Qu[ar * QS_STR + kc + 4];
            uint32_t a3 = Qu[(ar + 8) * QS_STR + kc + 4];
            #pragma unroll
            for (int j = 0; j < 8; j++) {
                const int n = (j << 3) + lr;
                mma_tf32(sc[j][0], sc[j][1], sc[j][2], sc[j][3],
                         a0, a1, a2, a3,
                         Ku[n * QS_STR + kc], Ku[n * QS_STR + kc + 4]);
            }
        }

        if (t == qt) {   // diagonal tile: causal mask
            #pragma unroll
            for (int j = 0; j < 8; j++) {
                const int c0 = (j << 3) + (lq << 1);
                const int r0 = wm + lr;
                if (c0 > r0)         sc[j][0] = -1e30f;
                if (c0 + 1 > r0)     sc[j][1] = -1e30f;
                if (c0 > r0 + 8)     sc[j][2] = -1e30f;
                if (c0 + 1 > r0 + 8) sc[j][3] = -1e30f;
            }
        }

        __syncwarp();   // prior PV reads of Ps complete (warp-private rows)

        // static softmax: P = exp2(s'), per-thread partial row sums
        #pragma unroll
        for (int h = 0; h < 2; h++) {
            float rs = 0.f;
            #pragma unroll
            for (int j = 0; j < 8; j++) {
                float e0 = ex2(sc[j][2 * h]);
                float e1 = ex2(sc[j][2 * h + 1]);
                rs += e0 + e1;
                *(float2*)&Ps[(wm + lr + 8 * h) * QS_STR + (j << 3) + (lq << 1)] =
                    make_float2(e0, e1);   // raw fp32; mma truncates to tf32
            }
            lrow[h] += rs;
        }
        __syncwarp();

        // O += P @ V
        #pragma unroll
        for (int ks = 0; ks < 8; ks++) {
            const int kc = (ks << 3) + lq;
            const int ar = wm + lr;
            uint32_t a0 = Pu[ar * QS_STR + kc];
            uint32_t a1 = Pu[(ar + 8) * QS_STR + kc];
            uint32_t a2 = Pu[ar * QS_STR + kc + 4];
            uint32_t a3 = Pu[(ar + 8) * QS_STR + kc + 4];
            #pragma unroll
            for (int j = 0; j < 8; j++) {
                const int n = (j << 3) + lr;
                mma_tf32(oacc[j][0], oacc[j][1], oacc[j][2], oacc[j][3],
                         a0, a1, a2, a3,
                         Vu[kc * VS_STR + n], Vu[(kc + 4) * VS_STR + n]);
            }
        }
        __syncthreads();   // K/V buffer reads done before next overwrite
    }

    // deferred lrow warp reduction (4-lane groups share a row)
    #pragma unroll
    for (int h = 0; h < 2; h++) {
        lrow[h] += __shfl_xor_sync(0xffffffffu, lrow[h], 1);
        lrow[h] += __shfl_xor_sync(0xffffffffu, lrow[h], 2);
    }

    const int b = bh >> 4;
    const int h = bh & 15;
    float* Ob = O + ((size_t)(b * SS + q0)) * DD + h * HDD;
    const float inv0 = 1.f / lrow[0];
    const float inv1 = 1.f / lrow[1];
    #pragma unroll
    for (int j = 0; j < 8; j++) {
        const int col = (j << 3) + (lq << 1);
        const int row = wm + lr;
        *(float2*)&Ob[(size_t)row * DD + col] =
            make_float2(tf32r(oacc[j][0] * inv0), tf32r(oacc[j][1] * inv0));
        *(float2*)&Ob[(size_t)(row + 8) * DD + col] =
            make_float2(tf32r(oacc[j][2] * inv1), tf32r(oacc[j][3] * inv1));
    }
}

// ---------------------------------------------------------------------------
// Launch
// ---------------------------------------------------------------------------
extern "C" void kernel_launch(void* const* d_in, const int* in_sizes, int n_in,
                              void* d_out, int out_size)
{
    const float* x      = (const float*)d_in[0];
    // d_in[1] = attn_mask (bool tril) — causal, handled analytically
    const float* freqs  = (const float*)d_in[2];
    const float* w_qkv  = (const float*)d_in[3];
    const float* b_qkv  = (const float*)d_in[4];
    const float* w_proj = (const float*)d_in[5];
    const float* b_proj = (const float*)d_in[6];
    float* out = (float*)d_out;

    float *q_p, *k_p, *v_p, *attn_p, *xr_p, *wqkvr_p, *wprojr_p;
    float2* cs_p;
    cudaGetSymbolAddress((void**)&q_p,      g_q);
    cudaGetSymbolAddress((void**)&k_p,      g_k);
    cudaGetSymbolAddress((void**)&v_p,      g_v);
    cudaGetSymbolAddress((void**)&attn_p,   g_attn);
    cudaGetSymbolAddress((void**)&xr_p,     g_xr);
    cudaGetSymbolAddress((void**)&wqkvr_p,  g_wqkvr);
    cudaGetSymbolAddress((void**)&wprojr_p, g_wprojr);
    cudaGetSymbolAddress((void**)&cs_p,     g_cs);

    cudaFuncSetAttribute(gemm_mma_tf32,
                         cudaFuncAttributeMaxDynamicSharedMemorySize, GEMM_SMEM);
    cudaFuncSetAttribute(gemm_qkv_rope,
                         cudaFuncAttributeMaxDynamicSharedMemorySize, GEMM_SMEM);
    cudaFuncSetAttribute(flash_mma_kernel,
                         cudaFuncAttributeMaxDynamicSharedMemorySize, FA_SMEM);

    // 0) fused prep: tf32-round operands + cos/sin table (1 launch)
    prep_kernel<<<(NPREP + 255) / 256, 256>>>(
        (const float4*)x, (const float4*)w_qkv, (const float4*)w_proj, freqs,
        (float4*)xr_p, (float4*)wqkvr_p, (float4*)wprojr_p, cs_p);

    // 1) QKV GEMM + fused RoPE/split -> q,k,v in [B,H,S,HD]
    gemm_qkv_rope<<<dim3(NQKV / 128, MTOT / 128), 256, GEMM_SMEM>>>(
        xr_p, wqkvr_p, b_qkv, cs_p, q_p, k_p, v_p, DD);

    // 2) Causal flash attention (tf32 mma, static exp2 softmax) -> [B,S,D]
    flash_mma_kernel<<<dim3(SS / 64, BB * HH), 128, FA_SMEM>>>(
        q_p, k_p, v_p, attn_p);

    // 3) out = attn @ w_proj^T + b_proj (ldmatrix mainloop)
    gemm_mma_tf32<<<dim3(DD / 128, MTOT / 128), 256, GEMM_SMEM>>>(
        attn_p, wprojr_p, b_proj, out, MTOT, DD, DD);
}

// round 16
// speedup vs baseline: 1.2096x; 1.2096x over previous
#include <cuda_runtime.h>
#include <cstdint>
#include <math.h>

#define BB 2
#define SS 2048
#define DD 1024
#define HH 16
#define HDD 64
#define MTOT (BB * SS)      // 4096
#define NQKV (3 * DD)       // 3072

// ---------------- device scratch (no allocation allowed) -------------------
__device__ float g_q[BB * HH * SS * HDD];   // tf32-rounded, scaled by 0.125*log2(e)
__device__ float g_k[BB * HH * SS * HDD];   // tf32-rounded
__device__ float g_v[BB * HH * SS * HDD];   // tf32-rounded
__device__ float g_attn[MTOT * DD];         // flash out, tf32-rounded
__device__ float g_xr[MTOT * DD];           // tf32-rounded x
__device__ float g_wqkvr[NQKV * DD];        // tf32-rounded w_qkv
__device__ float g_wprojr[DD * DD];         // tf32-rounded w_proj
__device__ float2 g_cs[SS * (HDD / 2)];     // cos/sin table

// ---------------- helpers ---------------------------------------------------
__device__ __forceinline__ uint32_t smem_u32(const void* p) {
    uint32_t a;
    asm("{ .reg .u64 t; cvta.to.shared.u64 t, %1; cvt.u32.u64 %0, t; }"
        : "=r"(a) : "l"(p));
    return a;
}
__device__ __forceinline__ float tf32r(float x) {
    float y;
    asm("cvt.rna.tf32.f32 %0, %1;" : "=f"(y) : "f"(x));
    return y;
}
__device__ __forceinline__ float ex2(float x) {
    float y;
    asm("ex2.approx.f32 %0, %1;" : "=f"(y) : "f"(x));
    return y;
}
__device__ __forceinline__ void mma_tf32(
    float& c0, float& c1, float& c2, float& c3,
    uint32_t a0, uint32_t a1, uint32_t a2, uint32_t a3,
    uint32_t b0, uint32_t b1)
{
    asm volatile(
        "mma.sync.aligned.m16n8k8.row.col.f32.tf32.tf32.f32 "
        "{%0,%1,%2,%3}, {%4,%5,%6,%7}, {%8,%9}, {%0,%1,%2,%3};"
        : "+f"(c0), "+f"(c1), "+f"(c2), "+f"(c3)
        : "r"(a0), "r"(a1), "r"(a2), "r"(a3), "r"(b0), "r"(b1));
}
#define CPASYNC16(dst, src) \
    asm volatile("cp.async.cg.shared.global [%0], [%1], 16;" :: "r"(dst), "l"(src))
#define CPCOMMIT() asm volatile("cp.async.commit_group;")

// ---------------------------------------------------------------------------
// tf32 mma.sync GEMM mainloop (R11/R6 structure — FROZEN: scalar LDS beats
// ldmatrix here (R15), occupancy is register-bound at 2 CTAs/SM (R12)).
// ---------------------------------------------------------------------------
#define GSTAGES 3
#define GTILE_B 16384                        // 128*32*4
#define GSTAGE_B (2 * GTILE_B)               // 32768
#define GEMM_SMEM (GSTAGES * GSTAGE_B)       // 98304

__device__ __forceinline__ void g_load_stage(
    uint32_t sbase, const float* A, const float* W, int K,
    int bm, int bn, int buf, int it, int tid)
{
    uint32_t sa = sbase + buf * GSTAGE_B;
    uint32_t sw = sa + GTILE_B;
    const float* Ag = A + (size_t)bm * K + it * 32;
    const float* Wg = W + (size_t)bn * K + it * 32;
    #pragma unroll
    for (int i = 0; i < 4; i++) {
        int idx = tid + (i << 8);            // 0..1023
        int row = idx >> 3, cc = idx & 7;
        uint32_t off = (row * 32 + ((cc ^ (row & 7)) << 2)) * 4;
        CPASYNC16(sa + off, Ag + (size_t)row * K + (cc << 2));
        CPASYNC16(sw + off, Wg + (size_t)row * K + (cc << 2));
    }
    CPCOMMIT();
}

#define GEMM_MAINLOOP(A_, W_, K_)                                              \
    float acc[4][4][4];                                                        \
    _Pragma("unroll") for (int mi = 0; mi < 4; mi++)                           \
        _Pragma("unroll") for (int ni = 0; ni < 4; ni++)                       \
            _Pragma("unroll") for (int e = 0; e < 4; e++) acc[mi][ni][e] = 0.f;\
    const int niter = (K_) >> 5;                                               \
    for (int s = 0; s < GSTAGES; s++)                                          \
        g_load_stage(sb, A_, W_, K_, bm, bn, s, s, tid);                       \
    for (int i = 0; i < niter; i++) {                                          \
        const int buf = i % GSTAGES;                                           \
        asm volatile("cp.async.wait_group 2;" ::: "memory");                   \
        __syncthreads();                                                       \
        const uint32_t* As = (const uint32_t*)(smem + buf * GSTAGE_B);         \
        const uint32_t* Ws = (const uint32_t*)(smem + buf * GSTAGE_B + GTILE_B);\
        _Pragma("unroll")                                                      \
        for (int ks = 0; ks < 4; ks++) {                                       \
            const int c0 = (((ks << 1) ^ lr) << 2) + lq;                       \
            const int c1 = ((((ks << 1) | 1) ^ lr) << 2) + lq;                 \
            uint32_t af[4][4], bf[4][2];                                       \
            _Pragma("unroll") for (int mi = 0; mi < 4; mi++) {                 \
                const int r = (wm << 6) + (mi << 4) + lr;                      \
                af[mi][0] = As[r * 32 + c0];                                   \
                af[mi][1] = As[(r + 8) * 32 + c0];                             \
                af[mi][2] = As[r * 32 + c1];                                   \
                af[mi][3] = As[(r + 8) * 32 + c1];                             \
            }                                                                  \
            _Pragma("unroll") for (int ni = 0; ni < 4; ni++) {                 \
                const int n = (wn << 5) + (ni << 3) + lr;                      \
                bf[ni][0] = Ws[n * 32 + c0];                                   \
                bf[ni][1] = Ws[n * 32 + c1];                                   \
            }                                                                  \
            _Pragma("unroll") for (int mi = 0; mi < 4; mi++)                   \
                _Pragma("unroll") for (int ni = 0; ni < 4; ni++)               \
                    mma_tf32(acc[mi][ni][0], acc[mi][ni][1],                   \
                             acc[mi][ni][2], acc[mi][ni][3],                   \
                             af[mi][0], af[mi][1], af[mi][2], af[mi][3],       \
                             bf[ni][0], bf[ni][1]);                            \
        }                                                                      \
        __syncthreads();                                                       \
        if (i + GSTAGES < niter)                                               \
            g_load_stage(sb, A_, W_, K_, bm, bn, buf, i + GSTAGES, tid);       \
        else                                                                   \
            CPCOMMIT();                                                        \
    }

// ---------------------------------------------------------------------------
// Generic GEMM (proj): C = A @ W^T + bias
// ---------------------------------------------------------------------------
__global__ void __launch_bounds__(256, 2) gemm_mma_tf32(
    const float* __restrict__ A, const float* __restrict__ W,
    const float* __restrict__ bias, float* __restrict__ C,
    int M, int N, int K)
{
    extern __shared__ char smem[];
    uint32_t sb = smem_u32(smem);
    const int tid  = threadIdx.x;
    const int lane = tid & 31;
    const int wid  = tid >> 5;
    const int wm   = wid >> 2, wn = wid & 3;
    const int bm = blockIdx.y << 7, bn = blockIdx.x << 7;
    const int lr = lane >> 2, lq = lane & 3;

    GEMM_MAINLOOP(A, W, K)

    #pragma unroll
    for (int mi = 0; mi < 4; mi++) {
        const int row = bm + (wm << 6) + (mi << 4) + lr;
        #pragma unroll
        for (int ni = 0; ni < 4; ni++) {
            const int col = bn + (wn << 5) + (ni << 3) + (lq << 1);
            const float b0 = bias[col], b1 = bias[col + 1];
            *(float2*)&C[(size_t)row * N + col] =
                make_float2(acc[mi][ni][0] + b0, acc[mi][ni][1] + b1);
            *(float2*)&C[(size_t)(row + 8) * N + col] =
                make_float2(acc[mi][ni][2] + b0, acc[mi][ni][3] + b1);
        }
    }
}

// ---------------------------------------------------------------------------
// QKV GEMM with fused RoPE epilogue -> q (rot, *0.125*log2e), k (rot), v,
// all tf32-rounded, [B,H,S,HD] layout.
// ---------------------------------------------------------------------------
#define QSCALE (0.125f * 1.4426950408889634f)

__global__ void __launch_bounds__(256, 2) gemm_qkv_rope(
    const float* __restrict__ A, const float* __restrict__ W,
    const float* __restrict__ bias, const float2* __restrict__ cs,
    float* __restrict__ qo, float* __restrict__ ko, float* __restrict__ vo,
    int K)
{
    extern __shared__ char smem[];
    uint32_t sb = smem_u32(smem);
    const int tid  = threadIdx.x;
    const int lane = tid & 31;
    const int wid  = tid >> 5;
    const int wm   = wid >> 2, wn = wid & 3;
    const int bm = blockIdx.y << 7, bn = blockIdx.x << 7;
    const int lr = lane >> 2, lq = lane & 3;

    GEMM_MAINLOOP(A, W, K)

    const int sec = bn >> 10;   // 0=q, 1=k, 2=v (uniform per CTA)
    #pragma unroll
    for (int mi = 0; mi < 4; mi++) {
        #pragma unroll
        for (int ni = 0; ni < 4; ni++) {
            const int col = bn + (wn << 5) + (ni << 3) + (lq << 1);
            const int h   = (col >> 6) & 15;
            const int d2  = (col & 63) >> 1;
            const float b0 = bias[col], b1 = bias[col + 1];
            #pragma unroll
            for (int hf = 0; hf < 2; hf++) {
                const int row = bm + (wm << 6) + (mi << 4) + lr + (hf << 3);
                const int b = row >> 11, s = row & 2047;
                const float v0 = acc[mi][ni][2 * hf]     + b0;
                const float v1 = acc[mi][ni][2 * hf + 1] + b1;
                const size_t o =
                    ((size_t)((b * HH + h) * SS + s)) * HDD + (d2 << 1);
                if (sec == 2) {
                    *(float2*)&vo[o] = make_float2(tf32r(v0), tf32r(v1));
                } else {
                    const float2 t = cs[s * 32 + d2];
                    float r0 = v0 * t.x - v1 * t.y;
                    float r1 = v0 * t.y + v1 * t.x;
                    if (sec == 0) {
                        *(float2*)&qo[o] = make_float2(tf32r(r0 * QSCALE),
                                                       tf32r(r1 * QSCALE));
                    } else {
                        *(float2*)&ko[o] = make_float2(tf32r(r0), tf32r(r1));
                    }
                }
            }
        }
    }
}

// ---------------------------------------------------------------------------
// Fused prep: tf32-round x / w_qkv / w_proj + build cos/sin table. 1 launch.
// ---------------------------------------------------------------------------
#define NX4 (MTOT * DD / 4)                  // 1048576
#define NW4 (NQKV * DD / 4)                  // 786432
#define NP4 (DD * DD / 4)                    // 262144
#define NPREP (NX4 + NW4 + NP4)              // 2097152

__global__ void prep_kernel(
    const float4* __restrict__ x,  const float4* __restrict__ wq,
    const float4* __restrict__ wp, const float* __restrict__ freqs,
    float4* __restrict__ xr, float4* __restrict__ wqr,
    float4* __restrict__ wpr, float2* __restrict__ cs)
{
    const int i = blockIdx.x * blockDim.x + threadIdx.x;
    if (i < NPREP) {
        const float4* src;
        float4* dst;
        int j;
        if (i < NX4)            { src = x;  dst = xr;  j = i; }
        else if (i < NX4 + NW4) { src = wq; dst = wqr; j = i - NX4; }
        else                    { src = wp; dst = wpr; j = i - NX4 - NW4; }
        float4 v = src[j];
        v.x = tf32r(v.x); v.y = tf32r(v.y); v.z = tf32r(v.z); v.w = tf32r(v.w);
        dst[j] = v;
    }
    if (i < SS * 32) {
        float f = freqs[i];
        cs[i] = make_float2(cosf(f), sinf(f));
    }
}

// ---------------------------------------------------------------------------
// Flash attention — R14 winner with SINGLE barrier per KV tile:
// top-of-tile wait_group 0 + one __syncthreads, then issue the t+1 K/V
// cp.async (its buffer was last read at t-1, fenced by this barrier), then
// QK / static-exp2 softmax / PV with no bottom barrier. Prefetch distance
// (one full tile of compute) is unchanged; barrier count per tile halves.
// Static exp2 softmax (ex2.approx), raw-fp32 P (HW tf32 truncation),
// deferred lrow reduction, BQ=BK=64, 128 thr, heavy-tiles-first.
// smem 106496 B, 2 CTAs/SM.
// ---------------------------------------------------------------------------
#define QS_STR 68
#define VS_STR 72
#define FA_QS 0
#define FA_PS (64 * QS_STR)
#define FA_K0 (2 * 64 * QS_STR)            // + buf*64*QS_STR
#define FA_V0 (4 * 64 * QS_STR)            // + buf*64*VS_STR
#define FA_SMEM ((4 * 64 * QS_STR + 2 * 64 * VS_STR) * 4)   // 106496 bytes

__device__ __forceinline__ void fa_load_kv(
    uint32_t sbq, const float* Kb, const float* Vb, int k0, int buf, int tid)
{
    uint32_t ks = sbq + (FA_K0 + buf * 64 * QS_STR) * 4;
    uint32_t vs = sbq + (FA_V0 + buf * 64 * VS_STR) * 4;
    #pragma unroll
    for (int i = 0; i < 8; i++) {
        int idx = tid + (i << 7);          // 0..1023
        int r = idx >> 4, c4 = (idx & 15) << 2;
        CPASYNC16(ks + (r * QS_STR + c4) * 4, Kb + (size_t)(k0 + r) * HDD + c4);
        CPASYNC16(vs + (r * VS_STR + c4) * 4, Vb + (size_t)(k0 + r) * HDD + c4);
    }
    CPCOMMIT();
}

__global__ void __launch_bounds__(128) flash_mma_kernel(
    const float* __restrict__ Q, const float* __restrict__ K,
    const float* __restrict__ V, float* __restrict__ O)
{
    extern __shared__ float sm[];
    uint32_t sbq = smem_u32(sm);
    float* Qs = sm + FA_QS;
    float* Ps = sm + FA_PS;
    const uint32_t* Qu = (const uint32_t*)Qs;
    const uint32_t* Pu = (const uint32_t*)Ps;

    const int tid  = threadIdx.x;
    const int lane = tid & 31;
    const int wid  = tid >> 5;
    const int lr   = lane >> 2, lq = lane & 3;
    const int wm   = wid << 4;
    const int qt   = gridDim.x - 1 - blockIdx.x;   // heavy tiles first
    const int q0   = qt << 6;
    const int bh   = blockIdx.y;

    const float* Qb = Q + ((size_t)bh * SS + q0) * HDD;
    const float* Kb = K + (size_t)bh * SS * HDD;
    const float* Vb = V + (size_t)bh * SS * HDD;

    const int ntiles = qt + 1;
    fa_load_kv(sbq, Kb, Vb, 0, 0, tid);

    // Q tile (already rounded+scaled by 0.125*log2e); made visible to all
    // threads by the first in-loop barrier.
    #pragma unroll
    for (int i = 0; i < 8; i++) {
        int idx = tid + (i << 7);
        int r = idx >> 4, c4 = (idx & 15) << 2;
        float4 t = *(const float4*)(Qb + r * HDD + c4);
        *(float4*)&Qs[r * QS_STR + c4] = t;
    }

    float lrow[2], oacc[8][4];
    lrow[0] = lrow[1] = 0.f;          // per-thread partial; warp-reduced once
    #pragma unroll
    for (int j = 0; j < 8; j++)
        #pragma unroll
        for (int e = 0; e < 4; e++) oacc[j][e] = 0.f;

    for (int t = 0; t < ntiles; t++) {
        asm volatile("cp.async.wait_group 0;" ::: "memory");   // K/V[t] ready
        __syncthreads();   // + all warps past tile t-1 reads of buf (t+1)&1
        if (t + 1 < ntiles)
            fa_load_kv(sbq, Kb, Vb, (t + 1) << 6, (t + 1) & 1, tid);

        const uint32_t* Ku = (const uint32_t*)(sm + FA_K0 + (t & 1) * 64 * QS_STR);
        const uint32_t* Vu = (const uint32_t*)(sm + FA_V0 + (t & 1) * 64 * VS_STR);

        // S' = Q K^T  (log2-domain scores; warp: m16 x n64, k64)
        float sc[8][4];
        #pragma unroll
        for (int j = 0; j < 8; j++)
            #pragma unroll
            for (int e = 0; e < 4; e++) sc[j][e] = 0.f;
        #pragma unroll
        for (int ks = 0; ks < 8; ks++) {
            const int kc = (ks << 3) + lq;
            const int ar = wm + lr;
            uint32_t a0 = Qu[ar * QS_STR + kc];
            uint32_t a1 = Qu[(ar + 8) * QS_STR + kc];
            uint32_t a2 = Qu[ar * QS_STR + kc + 4];
            uint32_t a3 = Qu[(ar + 8) * QS_STR + kc + 4];
            #pragma unroll
            for (int j = 0; j < 8; j++) {
                const int n = (j << 3) + lr;
                mma_tf32(sc[j][0], sc[j][1], sc[j][2], sc[j][3],
                         a0, a1, a2, a3,
                         Ku[n * QS_STR + kc], Ku[n * QS_STR + kc + 4]);
            }
        }

        if (t == qt) {   // diagonal tile: causal mask
            #pragma unroll
            for (int j = 0; j < 8; j++) {
                const int c0 = (j << 3) + (lq << 1);
                const int r0 = wm + lr;
                if (c0 > r0)         sc[j][0] = -1e30f;
                if (c0 + 1 > r0)     sc[j][1] = -1e30f;
                if (c0 > r0 + 8)     sc[j][2] = -1e30f;
                if (c0 + 1 > r0 + 8) sc[j][3] = -1e30f;
            }
        }

        __syncwarp();   // prior PV reads of Ps complete (warp-private rows)

        // static softmax: P = exp2(s'), per-thread partial row sums
        #pragma unroll
        for (int h = 0; h < 2; h++) {
            float rs = 0.f;
            #pragma unroll
            for (int j = 0; j < 8; j++) {
                float e0 = ex2(sc[j][2 * h]);
                float e1 = ex2(sc[j][2 * h + 1]);
                rs += e0 + e1;
                *(float2*)&Ps[(wm + lr + 8 * h) * QS_STR + (j << 3) + (lq << 1)] =
                    make_float2(e0, e1);   // raw fp32; mma truncates to tf32
            }
            lrow[h] += rs;
        }
        __syncwarp();

        // O += P @ V
        #pragma unroll
        for (int ks = 0; ks < 8; ks++) {
            const int kc = (ks << 3) + lq;
            const int ar = wm + lr;
            uint32_t a0 = Pu[ar * QS_STR + kc];
            uint32_t a1 = Pu[(ar + 8) * QS_STR + kc];
            uint32_t a2 = Pu[ar * QS_STR + kc + 4];
            uint32_t a3 = Pu[(ar + 8) * QS_STR + kc + 4];
            #pragma unroll
            for (int j = 0; j < 8; j++) {
                const int n = (j << 3) + lr;
                mma_tf32(oacc[j][0], oacc[j][1], oacc[j][2], oacc[j][3],
                         a0, a1, a2, a3,
                         Vu[kc * VS_STR + n], Vu[(kc + 4) * VS_STR + n]);
            }
        }
        // no bottom barrier: next iter's top barrier fences buffer reuse
    }

    // deferred lrow warp reduction (4-lane groups share a row)
    #pragma unroll
    for (int h = 0; h < 2; h++) {
        lrow[h] += __shfl_xor_sync(0xffffffffu, lrow[h], 1);
        lrow[h] += __shfl_xor_sync(0xffffffffu, lrow[h], 2);
    }

    const int b = bh >> 4;
    const int h = bh & 15;
    float* Ob = O + ((size_t)(b * SS + q0)) * DD + h * HDD;
    const float inv0 = 1.f / lrow[0];
    const float inv1 = 1.f / lrow[1];
    #pragma unroll
    for (int j = 0; j < 8; j++) {
        const int col = (j << 3) + (lq << 1);
        const int row = wm + lr;
        *(float2*)&Ob[(size_t)row * DD + col] =
            make_float2(tf32r(oacc[j][0] * inv0), tf32r(oacc[j][1] * inv0));
        *(float2*)&Ob[(size_t)(row + 8) * DD + col] =
            make_float2(tf32r(oacc[j][2] * inv1), tf32r(oacc[j][3] * inv1));
    }
}

// ---------------------------------------------------------------------------
// Launch
// ---------------------------------------------------------------------------
extern "C" void kernel_launch(void* const* d_in, const int* in_sizes, int n_in,
                              void* d_out, int out_size)
{
    const float* x      = (const float*)d_in[0];
    // d_in[1] = attn_mask (bool tril) — causal, handled analytically
    const float* freqs  = (const float*)d_in[2];
    const float* w_qkv  = (const float*)d_in[3];
    const float* b_qkv  = (const float*)d_in[4];
    const float* w_proj = (const float*)d_in[5];
    const float* b_proj = (const float*)d_in[6];
    float* out = (float*)d_out;

    float *q_p, *k_p, *v_p, *attn_p, *xr_p, *wqkvr_p, *wprojr_p;
    float2* cs_p;
    cudaGetSymbolAddress((void**)&q_p,      g_q);
    cudaGetSymbolAddress((void**)&k_p,      g_k);
    cudaGetSymbolAddress((void**)&v_p,      g_v);
    cudaGetSymbolAddress((void**)&attn_p,   g_attn);
    cudaGetSymbolAddress((void**)&xr_p,     g_xr);
    cudaGetSymbolAddress((void**)&wqkvr_p,  g_wqkvr);
    cudaGetSymbolAddress((void**)&wprojr_p, g_wprojr);
    cudaGetSymbolAddress((void**)&cs_p,     g_cs);

    cudaFuncSetAttribute(gemm_mma_tf32,
                         cudaFuncAttributeMaxDynamicSharedMemorySize, GEMM_SMEM);
    cudaFuncSetAttribute(gemm_qkv_rope,
                         cudaFuncAttributeMaxDynamicSharedMemorySize, GEMM_SMEM);
    cudaFuncSetAttribute(flash_mma_kernel,
                         cudaFuncAttributeMaxDynamicSharedMemorySize, FA_SMEM);

    // 0) fused prep: tf32-round operands + cos/sin table (1 launch)
    prep_kernel<<<(NPREP + 255) / 256, 256>>>(
        (const float4*)x, (const float4*)w_qkv, (const float4*)w_proj, freqs,
        (float4*)xr_p, (float4*)wqkvr_p, (float4*)wprojr_p, cs_p);

    // 1) QKV GEMM + fused RoPE/split -> q,k,v in [B,H,S,HD]
    gemm_qkv_rope<<<dim3(NQKV / 128, MTOT / 128), 256, GEMM_SMEM>>>(
        xr_p, wqkvr_p, b_qkv, cs_p, q_p, k_p, v_p, DD);

    // 2) Causal flash attention (tf32 mma, static exp2 softmax) -> [B,S,D]
    flash_mma_kernel<<<dim3(SS / 64, BB * HH), 128, FA_SMEM>>>(
        q_p, k_p, v_p, attn_p);

    // 3) out = attn @ w_proj^T + b_proj
    gemm_mma_tf32<<<dim3(DD / 128, MTOT / 128), 256, GEMM_SMEM>>>(
        attn_p, wprojr_p, b_proj, out, MTOT, DD, DD);
}

// round 17
// speedup vs baseline: 1.3097x; 1.0828x over previous
#include <cuda_runtime.h>
#include <cstdint>
#include <math.h>

#define BB 2
#define SS 2048
#define DD 1024
#define HH 16
#define HDD 64
#define MTOT (BB * SS)      // 4096
#define NQKV (3 * DD)       // 3072

// ---------------- device scratch (no allocation allowed) -------------------
__device__ float g_q[BB * HH * SS * HDD];   // tf32-rounded, scaled by 0.125*log2(e)
__device__ float g_k[BB * HH * SS * HDD];   // tf32-rounded
__device__ float g_v[BB * HH * SS * HDD];   // tf32-rounded
__device__ float g_attn[MTOT * DD];         // flash out, tf32-rounded
__device__ float g_xr[MTOT * DD];           // tf32-rounded x
__device__ float g_wqkvr[NQKV * DD];        // tf32-rounded w_qkv
__device__ float g_wprojr[DD * DD];         // tf32-rounded w_proj
__device__ float2 g_cs[SS * (HDD / 2)];     // cos/sin table

// ---------------- helpers ---------------------------------------------------
__device__ __forceinline__ uint32_t smem_u32(const void* p) {
    uint32_t a;
    asm("{ .reg .u64 t; cvta.to.shared.u64 t, %1; cvt.u32.u64 %0, t; }"
        : "=r"(a) : "l"(p));
    return a;
}
__device__ __forceinline__ float tf32r(float x) {
    float y;
    asm("cvt.rna.tf32.f32 %0, %1;" : "=f"(y) : "f"(x));
    return y;
}
__device__ __forceinline__ float ex2(float x) {
    float y;
    asm("ex2.approx.f32 %0, %1;" : "=f"(y) : "f"(x));
    return y;
}
__device__ __forceinline__ void mma_tf32(
    float& c0, float& c1, float& c2, float& c3,
    uint32_t a0, uint32_t a1, uint32_t a2, uint32_t a3,
    uint32_t b0, uint32_t b1)
{
    asm volatile(
        "mma.sync.aligned.m16n8k8.row.col.f32.tf32.tf32.f32 "
        "{%0,%1,%2,%3}, {%4,%5,%6,%7}, {%8,%9}, {%0,%1,%2,%3};"
        : "+f"(c0), "+f"(c1), "+f"(c2), "+f"(c3)
        : "r"(a0), "r"(a1), "r"(a2), "r"(a3), "r"(b0), "r"(b1));
}
#define CPASYNC16(dst, src) \
    asm volatile("cp.async.cg.shared.global [%0], [%1], 16;" :: "r"(dst), "l"(src))
#define CPCOMMIT() asm volatile("cp.async.commit_group;")

// ---------------------------------------------------------------------------
// tf32 mma.sync GEMM mainloop (R11/R6 structure — FROZEN: scalar LDS beats
// ldmatrix here (R15), occupancy is register-bound at 2 CTAs/SM (R12)).
// ---------------------------------------------------------------------------
#define GSTAGES 3
#define GTILE_B 16384                        // 128*32*4
#define GSTAGE_B (2 * GTILE_B)               // 32768
#define GEMM_SMEM (GSTAGES * GSTAGE_B)       // 98304

__device__ __forceinline__ void g_load_stage(
    uint32_t sbase, const float* A, const float* W, int K,
    int bm, int bn, int buf, int it, int tid)
{
    uint32_t sa = sbase + buf * GSTAGE_B;
    uint32_t sw = sa + GTILE_B;
    const float* Ag = A + (size_t)bm * K + it * 32;
    const float* Wg = W + (size_t)bn * K + it * 32;
    #pragma unroll
    for (int i = 0; i < 4; i++) {
        int idx = tid + (i << 8);            // 0..1023
        int row = idx >> 3, cc = idx & 7;
        uint32_t off = (row * 32 + ((cc ^ (row & 7)) << 2)) * 4;
        CPASYNC16(sa + off, Ag + (size_t)row * K + (cc << 2));
        CPASYNC16(sw + off, Wg + (size_t)row * K + (cc << 2));
    }
    CPCOMMIT();
}

#define GEMM_MAINLOOP(A_, W_, K_)                                              \
    float acc[4][4][4];                                                        \
    _Pragma("unroll") for (int mi = 0; mi < 4; mi++)                           \
        _Pragma("unroll") for (int ni = 0; ni < 4; ni++)                       \
            _Pragma("unroll") for (int e = 0; e < 4; e++) acc[mi][ni][e] = 0.f;\
    const int niter = (K_) >> 5;                                               \
    for (int s = 0; s < GSTAGES; s++)                                          \
        g_load_stage(sb, A_, W_, K_, bm, bn, s, s, tid);                       \
    for (int i = 0; i < niter; i++) {                                          \
        const int buf = i % GSTAGES;                                           \
        asm volatile("cp.async.wait_group 2;" ::: "memory");                   \
        __syncthreads();                                                       \
        const uint32_t* As = (const uint32_t*)(smem + buf * GSTAGE_B);         \
        const uint32_t* Ws = (const uint32_t*)(smem + buf * GSTAGE_B + GTILE_B);\
        _Pragma("unroll")                                                      \
        for (int ks = 0; ks < 4; ks++) {                                       \
            const int c0 = (((ks << 1) ^ lr) << 2) + lq;                       \
            const int c1 = ((((ks << 1) | 1) ^ lr) << 2) + lq;                 \
            uint32_t af[4][4], bf[4][2];                                       \
            _Pragma("unroll") for (int mi = 0; mi < 4; mi++) {                 \
                const int r = (wm << 6) + (mi << 4) + lr;                      \
                af[mi][0] = As[r * 32 + c0];                                   \
                af[mi][1] = As[(r + 8) * 32 + c0];                             \
                af[mi][2] = As[r * 32 + c1];                                   \
                af[mi][3] = As[(r + 8) * 32 + c1];                             \
            }                                                                  \
            _Pragma("unroll") for (int ni = 0; ni < 4; ni++) {                 \
                const int n = (wn << 5) + (ni << 3) + lr;                      \
                bf[ni][0] = Ws[n * 32 + c0];                                   \
                bf[ni][1] = Ws[n * 32 + c1];                                   \
            }                                                                  \
            _Pragma("unroll") for (int mi = 0; mi < 4; mi++)                   \
                _Pragma("unroll") for (int ni = 0; ni < 4; ni++)               \
                    mma_tf32(acc[mi][ni][0], acc[mi][ni][1],                   \
                             acc[mi][ni][2], acc[mi][ni][3],                   \
                             af[mi][0], af[mi][1], af[mi][2], af[mi][3],       \
                             bf[ni][0], bf[ni][1]);                            \
        }                                                                      \
        __syncthreads();                                                       \
        if (i + GSTAGES < niter)                                               \
            g_load_stage(sb, A_, W_, K_, bm, bn, buf, i + GSTAGES, tid);       \
        else                                                                   \
            CPCOMMIT();                                                        \
    }

// ---------------------------------------------------------------------------
// Generic GEMM (proj): C = A @ W^T + bias
// ---------------------------------------------------------------------------
__global__ void __launch_bounds__(256, 2) gemm_mma_tf32(
    const float* __restrict__ A, const float* __restrict__ W,
    const float* __restrict__ bias, float* __restrict__ C,
    int M, int N, int K)
{
    extern __shared__ char smem[];
    uint32_t sb = smem_u32(smem);
    const int tid  = threadIdx.x;
    const int lane = tid & 31;
    const int wid  = tid >> 5;
    const int wm   = wid >> 2, wn = wid & 3;
    const int bm = blockIdx.y << 7, bn = blockIdx.x << 7;
    const int lr = lane >> 2, lq = lane & 3;

    GEMM_MAINLOOP(A, W, K)

    #pragma unroll
    for (int mi = 0; mi < 4; mi++) {
        const int row = bm + (wm << 6) + (mi << 4) + lr;
        #pragma unroll
        for (int ni = 0; ni < 4; ni++) {
            const int col = bn + (wn << 5) + (ni << 3) + (lq << 1);
            const float b0 = bias[col], b1 = bias[col + 1];
            *(float2*)&C[(size_t)row * N + col] =
                make_float2(acc[mi][ni][0] + b0, acc[mi][ni][1] + b1);
            *(float2*)&C[(size_t)(row + 8) * N + col] =
                make_float2(acc[mi][ni][2] + b0, acc[mi][ni][3] + b1);
        }
    }
}

// ---------------------------------------------------------------------------
// QKV GEMM with fused RoPE epilogue -> q (rot, *0.125*log2e), k (rot), v,
// all tf32-rounded, [B,H,S,HD] layout.
// ---------------------------------------------------------------------------
#define QSCALE (0.125f * 1.4426950408889634f)

__global__ void __launch_bounds__(256, 2) gemm_qkv_rope(
    const float* __restrict__ A, const float* __restrict__ W,
    const float* __restrict__ bias, const float2* __restrict__ cs,
    float* __restrict__ qo, float* __restrict__ ko, float* __restrict__ vo,
    int K)
{
    extern __shared__ char smem[];
    uint32_t sb = smem_u32(smem);
    const int tid  = threadIdx.x;
    const int lane = tid & 31;
    const int wid  = tid >> 5;
    const int wm   = wid >> 2, wn = wid & 3;
    const int bm = blockIdx.y << 7, bn = blockIdx.x << 7;
    const int lr = lane >> 2, lq = lane & 3;

    GEMM_MAINLOOP(A, W, K)

    const int sec = bn >> 10;   // 0=q, 1=k, 2=v (uniform per CTA)
    #pragma unroll
    for (int mi = 0; mi < 4; mi++) {
        #pragma unroll
        for (int ni = 0; ni < 4; ni++) {
            const int col = bn + (wn << 5) + (ni << 3) + (lq << 1);
            const int h   = (col >> 6) & 15;
            const int d2  = (col & 63) >> 1;
            const float b0 = bias[col], b1 = bias[col + 1];
            #pragma unroll
            for (int hf = 0; hf < 2; hf++) {
                const int row = bm + (wm << 6) + (mi << 4) + lr + (hf << 3);
                const int b = row >> 11, s = row & 2047;
                const float v0 = acc[mi][ni][2 * hf]     + b0;
                const float v1 = acc[mi][ni][2 * hf + 1] + b1;
                const size_t o =
                    ((size_t)((b * HH + h) * SS + s)) * HDD + (d2 << 1);
                if (sec == 2) {
                    *(float2*)&vo[o] = make_float2(tf32r(v0), tf32r(v1));
                } else {
                    const float2 t = cs[s * 32 + d2];
                    float r0 = v0 * t.x - v1 * t.y;
                    float r1 = v0 * t.y + v1 * t.x;
                    if (sec == 0) {
                        *(float2*)&qo[o] = make_float2(tf32r(r0 * QSCALE),
                                                       tf32r(r1 * QSCALE));
                    } else {
                        *(float2*)&ko[o] = make_float2(tf32r(r0), tf32r(r1));
                    }
                }
            }
        }
    }
}

// ---------------------------------------------------------------------------
// Fused prep: tf32-round x / w_qkv / w_proj + build cos/sin table. 1 launch.
// ---------------------------------------------------------------------------
#define NX4 (MTOT * DD / 4)                  // 1048576
#define NW4 (NQKV * DD / 4)                  // 786432
#define NP4 (DD * DD / 4)                    // 262144
#define NPREP (NX4 + NW4 + NP4)              // 2097152

__global__ void prep_kernel(
    const float4* __restrict__ x,  const float4* __restrict__ wq,
    const float4* __restrict__ wp, const float* __restrict__ freqs,
    float4* __restrict__ xr, float4* __restrict__ wqr,
    float4* __restrict__ wpr, float2* __restrict__ cs)
{
    const int i = blockIdx.x * blockDim.x + threadIdx.x;
    if (i < NPREP) {
        const float4* src;
        float4* dst;
        int j;
        if (i < NX4)            { src = x;  dst = xr;  j = i; }
        else if (i < NX4 + NW4) { src = wq; dst = wqr; j = i - NX4; }
        else                    { src = wp; dst = wpr; j = i - NX4 - NW4; }
        float4 v = src[j];
        v.x = tf32r(v.x); v.y = tf32r(v.y); v.z = tf32r(v.z); v.w = tf32r(v.w);
        dst[j] = v;
    }
    if (i < SS * 32) {
        float f = freqs[i];
        cs[i] = make_float2(cosf(f), sinf(f));
    }
}

// ---------------------------------------------------------------------------
// Flash attention — R16 winner (single barrier per tile) with GLOBAL LPT
// dispatch: 1D grid of 1024 CTAs sorted by descending tile count
// (qt = 31 - bid/32, bh = bid%32), so all 32-tile CTAs dispatch first and
// 1-tile CTAs backfill the tail. Static exp2 softmax (ex2.approx),
// raw-fp32 P (HW tf32 truncation), deferred lrow reduction, BQ=BK=64,
// 128 thr, cp.async double-buffered K/V. smem 106496 B, 2 CTAs/SM.
// ---------------------------------------------------------------------------
#define QS_STR 68
#define VS_STR 72
#define FA_QS 0
#define FA_PS (64 * QS_STR)
#define FA_K0 (2 * 64 * QS_STR)            // + buf*64*QS_STR
#define FA_V0 (4 * 64 * QS_STR)            // + buf*64*VS_STR
#define FA_SMEM ((4 * 64 * QS_STR + 2 * 64 * VS_STR) * 4)   // 106496 bytes

__device__ __forceinline__ void fa_load_kv(
    uint32_t sbq, const float* Kb, const float* Vb, int k0, int buf, int tid)
{
    uint32_t ks = sbq + (FA_K0 + buf * 64 * QS_STR) * 4;
    uint32_t vs = sbq + (FA_V0 + buf * 64 * VS_STR) * 4;
    #pragma unroll
    for (int i = 0; i < 8; i++) {
        int idx = tid + (i << 7);          // 0..1023
        int r = idx >> 4, c4 = (idx & 15) << 2;
        CPASYNC16(ks + (r * QS_STR + c4) * 4, Kb + (size_t)(k0 + r) * HDD + c4);
        CPASYNC16(vs + (r * VS_STR + c4) * 4, Vb + (size_t)(k0 + r) * HDD + c4);
    }
    CPCOMMIT();
}

__global__ void __launch_bounds__(128) flash_mma_kernel(
    const float* __restrict__ Q, const float* __restrict__ K,
    const float* __restrict__ V, float* __restrict__ O)
{
    extern __shared__ float sm[];
    uint32_t sbq = smem_u32(sm);
    float* Qs = sm + FA_QS;
    float* Ps = sm + FA_PS;
    const uint32_t* Qu = (const uint32_t*)Qs;
    const uint32_t* Pu = (const uint32_t*)Ps;

    const int tid  = threadIdx.x;
    const int lane = tid & 31;
    const int wid  = tid >> 5;
    const int lr   = lane >> 2, lq = lane & 3;
    const int wm   = wid << 4;
    // Global LPT dispatch order: heaviest (qt=31) CTAs first, all bh.
    const int bid  = blockIdx.x;
    const int qt   = 31 - (bid >> 5);
    const int bh   = bid & 31;
    const int q0   = qt << 6;

    const float* Qb = Q + ((size_t)bh * SS + q0) * HDD;
    const float* Kb = K + (size_t)bh * SS * HDD;
    const float* Vb = V + (size_t)bh * SS * HDD;

    const int ntiles = qt + 1;
    fa_load_kv(sbq, Kb, Vb, 0, 0, tid);

    // Q tile (already rounded+scaled by 0.125*log2e); made visible to all
    // threads by the first in-loop barrier.
    #pragma unroll
    for (int i = 0; i < 8; i++) {
        int idx = tid + (i << 7);
        int r = idx >> 4, c4 = (idx & 15) << 2;
        float4 t = *(const float4*)(Qb + r * HDD + c4);
        *(float4*)&Qs[r * QS_STR + c4] = t;
    }

    float lrow[2], oacc[8][4];
    lrow[0] = lrow[1] = 0.f;          // per-thread partial; warp-reduced once
    #pragma unroll
    for (int j = 0; j < 8; j++)
        #pragma unroll
        for (int e = 0; e < 4; e++) oacc[j][e] = 0.f;

    for (int t = 0; t < ntiles; t++) {
        asm volatile("cp.async.wait_group 0;" ::: "memory");   // K/V[t] ready
        __syncthreads();   // + all warps past tile t-1 reads of buf (t+1)&1
        if (t + 1 < ntiles)
            fa_load_kv(sbq, Kb, Vb, (t + 1) << 6, (t + 1) & 1, tid);

        const uint32_t* Ku = (const uint32_t*)(sm + FA_K0 + (t & 1) * 64 * QS_STR);
        const uint32_t* Vu = (const uint32_t*)(sm + FA_V0 + (t & 1) * 64 * VS_STR);

        // S' = Q K^T  (log2-domain scores; warp: m16 x n64, k64)
        float sc[8][4];
        #pragma unroll
        for (int j = 0; j < 8; j++)
            #pragma unroll
            for (int e = 0; e < 4; e++) sc[j][e] = 0.f;
        #pragma unroll
        for (int ks = 0; ks < 8; ks++) {
            const int kc = (ks << 3) + lq;
            const int ar = wm + lr;
            uint32_t a0 = Qu[ar * QS_STR + kc];
            uint32_t a1 = Qu[(ar + 8) * QS_STR + kc];
            uint32_t a2 = Qu[ar * QS_STR + kc + 4];
            uint32_t a3 = Qu[(ar + 8) * QS_STR + kc + 4];
            #pragma unroll
            for (int j = 0; j < 8; j++) {
                const int n = (j << 3) + lr;
                mma_tf32(sc[j][0], sc[j][1], sc[j][2], sc[j][3],
                         a0, a1, a2, a3,
                         Ku[n * QS_STR + kc], Ku[n * QS_STR + kc + 4]);
            }
        }

        if (t == qt) {   // diagonal tile: causal mask
            #pragma unroll
            for (int j = 0; j < 8; j++) {
                const int c0 = (j << 3) + (lq << 1);
                const int r0 = wm + lr;
                if (c0 > r0)         sc[j][0] = -1e30f;
                if (c0 + 1 > r0)     sc[j][1] = -1e30f;
                if (c0 > r0 + 8)     sc[j][2] = -1e30f;
                if (c0 + 1 > r0 + 8) sc[j][3] = -1e30f;
            }
        }

        __syncwarp();   // prior PV reads of Ps complete (warp-private rows)

        // static softmax: P = exp2(s'), per-thread partial row sums
        #pragma unroll
        for (int h = 0; h < 2; h++) {
            float rs = 0.f;
            #pragma unroll
            for (int j = 0; j < 8; j++) {
                float e0 = ex2(sc[j][2 * h]);
                float e1 = ex2(sc[j][2 * h + 1]);
                rs += e0 + e1;
                *(float2*)&Ps[(wm + lr + 8 * h) * QS_STR + (j << 3) + (lq << 1)] =
                    make_float2(e0, e1);   // raw fp32; mma truncates to tf32
            }
            lrow[h] += rs;
        }
        __syncwarp();

        // O += P @ V
        #pragma unroll
        for (int ks = 0; ks < 8; ks++) {
            const int kc = (ks << 3) + lq;
            const int ar = wm + lr;
            uint32_t a0 = Pu[ar * QS_STR + kc];
            uint32_t a1 = Pu[(ar + 8) * QS_STR + kc];
            uint32_t a2 = Pu[ar * QS_STR + kc + 4];
            uint32_t a3 = Pu[(ar + 8) * QS_STR + kc + 4];
            #pragma unroll
            for (int j = 0; j < 8; j++) {
                const int n = (j << 3) + lr;
                mma_tf32(oacc[j][0], oacc[j][1], oacc[j][2], oacc[j][3],
                         a0, a1, a2, a3,
                         Vu[kc * VS_STR + n], Vu[(kc + 4) * VS_STR + n]);
            }
        }
        // no bottom barrier: next iter's top barrier fences buffer reuse
    }

    // deferred lrow warp reduction (4-lane groups share a row)
    #pragma unroll
    for (int h = 0; h < 2; h++) {
        lrow[h] += __shfl_xor_sync(0xffffffffu, lrow[h], 1);
        lrow[h] += __shfl_xor_sync(0xffffffffu, lrow[h], 2);
    }

    const int b = bh >> 4;
    const int h = bh & 15;
    float* Ob = O + ((size_t)(b * SS + q0)) * DD + h * HDD;
    const float inv0 = 1.f / lrow[0];
    const float inv1 = 1.f / lrow[1];
    #pragma unroll
    for (int j = 0; j < 8; j++) {
        const int col = (j << 3) + (lq << 1);
        const int row = wm + lr;
        *(float2*)&Ob[(size_t)row * DD + col] =
            make_float2(tf32r(oacc[j][0] * inv0), tf32r(oacc[j][1] * inv0));
        *(float2*)&Ob[(size_t)(row + 8) * DD + col] =
            make_float2(tf32r(oacc[j][2] * inv1), tf32r(oacc[j][3] * inv1));
    }
}

// ---------------------------------------------------------------------------
// Launch
// ---------------------------------------------------------------------------
extern "C" void kernel_launch(void* const* d_in, const int* in_sizes, int n_in,
                              void* d_out, int out_size)
{
    const float* x      = (const float*)d_in[0];
    // d_in[1] = attn_mask (bool tril) — causal, handled analytically
    const float* freqs  = (const float*)d_in[2];
    const float* w_qkv  = (const float*)d_in[3];
    const float* b_qkv  = (const float*)d_in[4];
    const float* w_proj = (const float*)d_in[5];
    const float* b_proj = (const float*)d_in[6];
    float* out = (float*)d_out;

    float *q_p, *k_p, *v_p, *attn_p, *xr_p, *wqkvr_p, *wprojr_p;
    float2* cs_p;
    cudaGetSymbolAddress((void**)&q_p,      g_q);
    cudaGetSymbolAddress((void**)&k_p,      g_k);
    cudaGetSymbolAddress((void**)&v_p,      g_v);
    cudaGetSymbolAddress((void**)&attn_p,   g_attn);
    cudaGetSymbolAddress((void**)&xr_p,     g_xr);
    cudaGetSymbolAddress((void**)&wqkvr_p,  g_wqkvr);
    cudaGetSymbolAddress((void**)&wprojr_p, g_wprojr);
    cudaGetSymbolAddress((void**)&cs_p,     g_cs);

    cudaFuncSetAttribute(gemm_mma_tf32,
                         cudaFuncAttributeMaxDynamicSharedMemorySize, GEMM_SMEM);
    cudaFuncSetAttribute(gemm_qkv_rope,
                         cudaFuncAttributeMaxDynamicSharedMemorySize, GEMM_SMEM);
    cudaFuncSetAttribute(flash_mma_kernel,
                         cudaFuncAttributeMaxDynamicSharedMemorySize, FA_SMEM);

    // 0) fused prep: tf32-round operands + cos/sin table (1 launch)
    prep_kernel<<<(NPREP + 255) / 256, 256>>>(
        (const float4*)x, (const float4*)w_qkv, (const float4*)w_proj, freqs,
        (float4*)xr_p, (float4*)wqkvr_p, (float4*)wprojr_p, cs_p);

    // 1) QKV GEMM + fused RoPE/split -> q,k,v in [B,H,S,HD]
    gemm_qkv_rope<<<dim3(NQKV / 128, MTOT / 128), 256, GEMM_SMEM>>>(
        xr_p, wqkvr_p, b_qkv, cs_p, q_p, k_p, v_p, DD);

    // 2) Causal flash attention (tf32 mma, global LPT dispatch) -> [B,S,D]
    flash_mma_kernel<<<(SS / 64) * BB * HH, 128, FA_SMEM>>>(
        q_p, k_p, v_p, attn_p);

    // 3) out = attn @ w_proj^T + b_proj
    gemm_mma_tf32<<<dim3(DD / 128, MTOT / 128), 256, GEMM_SMEM>>>(
        attn_p, wprojr_p, b_proj, out, MTOT, DD, DD);
}